// round 12
// baseline (speedup 1.0000x reference)
#include <cuda_runtime.h>
#include <cuda_bf16.h>
#include <cstdint>

#define N_PTS 400000
#define DIM   128
#define KNB   27
#define NSEG  8
#define MTILE 128
#define CTHR  512
#define NTHR  256
#define NBLK  (N_PTS / MTILE)
#define FTILE 64

// ---------------- scratch (static device globals: allocation-free) ----------------
__device__ float g_out1[(size_t)N_PTS * DIM];
__device__ float g_out2[(size_t)N_PTS * DIM];
__device__ float g_segsum[NSEG * DIM];
__device__ float g_segmean[NSEG * DIM];
__device__ int   g_segcnt[NSEG];
__device__ __nv_bfloat16 g_fhi[(size_t)N_PTS * DIM];
__device__ __nv_bfloat16 g_flo[(size_t)N_PTS * DIM];
// W images: [k][part(hi/lo)][conv] 32KB tiles -> hi pair contiguous, lo pair contiguous
__device__ __nv_bfloat16 g_Wimg[(size_t)KNB * 2 * 2 * 16384];
// W3 image: [part(hi/lo)] 32KB tiles (128 rows x 256B each)
__device__ __nv_bfloat16 g_W3img[2 * 16384];

// ---------------- smem layout for conv kernel (bytes) ----------------
#define SM_MB    0          // mbars: WH@0 WL@8
#define SM_AHI0  1024
#define SM_AHI1  (SM_AHI0 + 32768)   // 33792
#define SM_ALO   (SM_AHI1 + 32768)   // 66560
#define SM_WH    (SM_ALO + 32768)    // 99328  (W1h, W2h@+32768)
#define SM_WL    (SM_WH + 65536)     // 164864 (W1l, W2l@+32768)
#define SM_TOTAL (SM_WL + 65536)     // 230400

// ---------------- smem layout for finalize kernel (bytes) ----------------
#define FM_W3H 0                                // 32KB
#define FM_W3L 32768                            // 32KB
#define FM_AH  65536                            // 16KB (64 rows x 256B)
#define FM_AL  81920                            // 16KB
#define FM_RED 98304                            // 256 floats
#define FM_RM  (FM_RED + NTHR * 4)              // 64 floats
#define FM_TOT (FM_RM + FTILE * 4)              // 99584

// fused pre-pass block ranges
#define PP_ZERO   4
#define PP_SPLIT  ((N_PTS * DIM) / (NTHR * 4))          // 50000
#define PP_W      ((KNB * 2 * DIM * DIM) / NTHR)        // 3456
#define PP_W3     ((DIM * DIM) / NTHR)                  // 64
#define PP_TOTAL  (PP_ZERO + PP_SPLIT + PP_W + PP_W3)   // 53524

__device__ __forceinline__ uint32_t smem_u32(const void* p) {
    return (uint32_t)__cvta_generic_to_shared(p);
}

// ---------------- PTX helpers (baseline sm_80/sm_90 features only) ----------------
#define MBAR_INIT(a, c) \
    asm volatile("mbarrier.init.shared.b64 [%0], %1;" :: "r"(a), "r"(c) : "memory")
#define MBAR_EXPECT_TX(a, b) \
    asm volatile("mbarrier.arrive.expect_tx.shared.b64 _, [%0], %1;" :: "r"(a), "r"(b) : "memory")
#define MBAR_WAIT(a, ph) do {                                                 \
    uint32_t _m = (a), _p = (ph), _d;                                         \
    asm volatile("{\n .reg .pred p;\n"                                        \
        " mbarrier.try_wait.parity.acquire.cta.shared::cta.b64 p, [%1], %2;\n"\
        " selp.b32 %0, 1, 0, p;\n}" : "=r"(_d) : "r"(_m), "r"(_p) : "memory");\
    if (!_d) {                                                                \
        asm volatile("{\n .reg .pred P1;\n"                                   \
        "W%=:\n mbarrier.try_wait.parity.acquire.cta.shared::cta.b64 P1, [%0], %1, 0x989680;\n" \
        " @P1 bra.uni D%=;\n bra.uni W%=;\nD%=:\n}" :: "r"(_m), "r"(_p) : "memory"); \
    } } while (0)

#define CP_COMMIT() asm volatile("cp.async.commit_group;" ::: "memory")
#define CP_WAIT(n)  asm volatile("cp.async.wait_group %0;" :: "n"(n) : "memory")

__device__ __forceinline__ void cp16z(uint32_t dst, const void* src, uint32_t srcsz) {
    asm volatile("cp.async.cg.shared.global [%0], [%1], 16, %2;"
                 :: "r"(dst), "l"(src), "r"(srcsz) : "memory");
}
__device__ __forceinline__ void bulk_g2s(uint32_t dst, const void* src,
                                         uint32_t bytes, uint32_t mbar) {
    asm volatile(
        "cp.async.bulk.shared::cluster.global.mbarrier::complete_tx::bytes "
        "[%0], [%1], %2, [%3];"
        :: "r"(dst), "l"(src), "r"(bytes), "r"(mbar) : "memory");
}
__device__ __forceinline__ void ldsm4(uint32_t* r, uint32_t addr) {
    asm volatile("ldmatrix.sync.aligned.m8n8.x4.shared.b16 {%0,%1,%2,%3}, [%4];"
        : "=r"(r[0]), "=r"(r[1]), "=r"(r[2]), "=r"(r[3]) : "r"(addr));
}
__device__ __forceinline__ void mma_bf16(float* c, const uint32_t* a, const uint32_t* b) {
    asm volatile("mma.sync.aligned.m16n8k16.row.col.f32.bf16.bf16.f32 "
        "{%0,%1,%2,%3}, {%4,%5,%6,%7}, {%8,%9}, {%0,%1,%2,%3};"
        : "+f"(c[0]), "+f"(c[1]), "+f"(c[2]), "+f"(c[3])
        : "r"(a[0]), "r"(a[1]), "r"(a[2]), "r"(a[3]), "r"(b[0]), "r"(b[1]));
}
__device__ __forceinline__ uint32_t packbf2(float lo, float hi) {
    uint32_t r;
    asm("cvt.rn.bf16x2.f32 %0, %1, %2;" : "=r"(r) : "f"(hi), "f"(lo));
    return r;
}

// ---------------- fused pre-pass: zero | split feats | prep W | prep W3 ----------
__global__ void pre_pass_kernel(const float* __restrict__ feats,
                                const float* __restrict__ W1,
                                const float* __restrict__ W2,
                                const float* __restrict__ W3) {
    const uint32_t bid = blockIdx.x;
    const uint32_t tid = threadIdx.x;
    if (bid < PP_ZERO) {
        const uint32_t t = bid * NTHR + tid;   // 0..1023
        if (t < NSEG * DIM) g_segsum[t] = 0.f;
        if (t < NSEG) g_segcnt[t] = 0;
        return;
    }
    if (bid < PP_ZERO + PP_SPLIT) {
        const size_t i = ((size_t)(bid - PP_ZERO) * NTHR + tid) * 4;
        const float4 v = *reinterpret_cast<const float4*>(feats + i);
        const float hx = __bfloat162float(__float2bfloat16(v.x));
        const float hy = __bfloat162float(__float2bfloat16(v.y));
        const float hz = __bfloat162float(__float2bfloat16(v.z));
        const float hw = __bfloat162float(__float2bfloat16(v.w));
        uint2 hi, lo;
        hi.x = packbf2(v.x, v.y);       hi.y = packbf2(v.z, v.w);
        lo.x = packbf2(v.x - hx, v.y - hy);
        lo.y = packbf2(v.z - hz, v.w - hw);
        *reinterpret_cast<uint2*>(g_fhi + i) = hi;
        *reinterpret_cast<uint2*>(g_flo + i) = lo;
        return;
    }
    if (bid < PP_ZERO + PP_SPLIT + PP_W) {
        // W -> transposed, split, SMEM-image; tile index = k*4 + part*2 + conv
        const uint32_t t = (bid - PP_ZERO - PP_SPLIT) * NTHR + tid;
        const uint32_t d = t & 127;
        const uint32_t n = (t >> 7) & 127;
        const uint32_t conv = (t >> 14) & 1;
        const uint32_t k = t >> 15;
        const float w = (conv ? W2 : W1)[((size_t)k * DIM + d) * DIM + n];
        const float hf = __bfloat162float(__float2bfloat16(w));
        const uint32_t off = n * 256 + ((((d >> 3) ^ (n & 7)) << 4)) + (d & 7) * 2;
        const size_t khi = (size_t)(k * 4 + conv);
        const size_t klo = (size_t)(k * 4 + 2 + conv);
        g_Wimg[khi * 16384 + (off >> 1)] = __float2bfloat16(w);
        g_Wimg[klo * 16384 + (off >> 1)] = __float2bfloat16(w - hf);
        return;
    }
    {
        const uint32_t t = (bid - PP_ZERO - PP_SPLIT - PP_W) * NTHR + tid;
        const uint32_t n = t & 127;
        const uint32_t d = t >> 7;
        const float w = W3[(size_t)d * DIM + n];
        const float hf = __bfloat162float(__float2bfloat16(w));
        const uint32_t off = n * 256 + ((((d >> 3) ^ (n & 7)) << 4)) + (d & 7) * 2;
        g_W3img[off >> 1]           = __float2bfloat16(w);
        g_W3img[16384 + (off >> 1)] = __float2bfloat16(w - hf);
    }
}

// ---------------- A staging via cp.async zfill; idx/mask straight from gmem -------
__device__ __forceinline__ void stage_A_cp(uint32_t sb, uint32_t a_base,
                                           const __nv_bfloat16* fsrc,
                                           const int* __restrict__ nidx,
                                           const int* __restrict__ nmask,
                                           size_t ebase, int k) {
    const int t = threadIdx.x;
    const int r = t >> 2;                  // row 0..127
    const int q = t & 3;                   // 4 chunks per thread
    const size_t e = ebase + (size_t)r * KNB + k;
    const int id = __ldg(nidx + e);
    const uint32_t sz = __ldg(nmask + e) ? 16u : 0u;
    const char* src = reinterpret_cast<const char*>(fsrc + (size_t)id * DIM) + q * 64;
    const uint32_t drow = sb + a_base + (uint32_t)r * 256;
    const uint32_t x = (uint32_t)(r & 7);
#pragma unroll
    for (int c2 = 0; c2 < 4; c2++) {
        const uint32_t c = (uint32_t)(q * 4 + c2);
        cp16z(drow + ((c ^ x) << 4), src + c2 * 16, sz);
    }
}

// ---------------- fused AB: (Alo + Ahi) x (W1h, W2h).  8 ldsm / 32 MMA per kc -----
__device__ __forceinline__ void mma_ab(uint32_t sb, uint32_t ahi_base,
                                       float acc[2][2][4][4],
                                       uint32_t a_row, uint32_t b_row,
                                       uint32_t ahalf, uint32_t bhalf, uint32_t xr) {
#pragma unroll
    for (uint32_t kc = 0; kc < 8; kc++) {
        const uint32_t ach = ((2 * kc + ahalf) ^ xr) << 4;
        const uint32_t bch = ((2 * kc + bhalf) ^ xr) << 4;
        uint32_t lo0[4], lo1[4], hi0[4], hi1[4], w1[8], w2[8];
        ldsm4(lo0, sb + SM_ALO + a_row + ach);
        ldsm4(lo1, sb + SM_ALO + a_row + 4096 + ach);
        ldsm4(hi0, sb + ahi_base + a_row + ach);
        ldsm4(hi1, sb + ahi_base + a_row + 4096 + ach);
        ldsm4(&w1[0], sb + SM_WH + b_row + bch);
        ldsm4(&w1[4], sb + SM_WH + b_row + 4096 + bch);
        ldsm4(&w2[0], sb + SM_WH + 32768 + b_row + bch);
        ldsm4(&w2[4], sb + SM_WH + 32768 + b_row + 4096 + bch);
#pragma unroll
        for (int j = 0; j < 4; j++) {
            mma_bf16(acc[0][0][j], lo0, &w1[j * 2]);
            mma_bf16(acc[0][1][j], lo1, &w1[j * 2]);
            mma_bf16(acc[1][0][j], lo0, &w2[j * 2]);
            mma_bf16(acc[1][1][j], lo1, &w2[j * 2]);
            mma_bf16(acc[0][0][j], hi0, &w1[j * 2]);
            mma_bf16(acc[0][1][j], hi1, &w1[j * 2]);
            mma_bf16(acc[1][0][j], hi0, &w2[j * 2]);
            mma_bf16(acc[1][1][j], hi1, &w2[j * 2]);
        }
    }
}

// ---------------- phase C: Ahi x (W1l, W2l).  6 ldsm / 16 MMA per kc --------------
__device__ __forceinline__ void mma_c(uint32_t sb, uint32_t ahi_base,
                                      float acc[2][2][4][4],
                                      uint32_t a_row, uint32_t b_row,
                                      uint32_t ahalf, uint32_t bhalf, uint32_t xr) {
#pragma unroll
    for (uint32_t kc = 0; kc < 8; kc++) {
        const uint32_t ach = ((2 * kc + ahalf) ^ xr) << 4;
        const uint32_t bch = ((2 * kc + bhalf) ^ xr) << 4;
        uint32_t a0[4], a1[4], w1[8], w2[8];
        ldsm4(a0, sb + ahi_base + a_row + ach);
        ldsm4(a1, sb + ahi_base + a_row + 4096 + ach);
        ldsm4(&w1[0], sb + SM_WL + b_row + bch);
        ldsm4(&w1[4], sb + SM_WL + b_row + 4096 + bch);
        ldsm4(&w2[0], sb + SM_WL + 32768 + b_row + bch);
        ldsm4(&w2[4], sb + SM_WL + 32768 + b_row + 4096 + bch);
#pragma unroll
        for (int j = 0; j < 4; j++) {
            mma_bf16(acc[0][0][j], a0, &w1[j * 2]);
            mma_bf16(acc[0][1][j], a1, &w1[j * 2]);
            mma_bf16(acc[1][0][j], a0, &w2[j * 2]);
            mma_bf16(acc[1][1][j], a1, &w2[j * 2]);
        }
    }
}

// ---------------- MMA product groups (used by finalize) ----------------
__device__ __forceinline__ void mma_group1(uint32_t sb, uint32_t a_base, uint32_t w_base,
                                           float acc[2][4][4],
                                           uint32_t a_row, uint32_t b_row,
                                           uint32_t ahalf, uint32_t bhalf, uint32_t xr) {
#pragma unroll
    for (uint32_t kc = 0; kc < 8; kc++) {
        const uint32_t ach = ((2 * kc + ahalf) ^ xr) << 4;
        const uint32_t bch = ((2 * kc + bhalf) ^ xr) << 4;
        uint32_t a0[4], a1[4], wb[8];
        ldsm4(a0, sb + a_base + a_row + ach);
        ldsm4(a1, sb + a_base + a_row + 4096 + ach);
        ldsm4(&wb[0], sb + w_base + b_row + bch);
        ldsm4(&wb[4], sb + w_base + b_row + 4096 + bch);
#pragma unroll
        for (int j = 0; j < 4; j++) {
            mma_bf16(acc[0][j], a0, &wb[j * 2]);
            mma_bf16(acc[1][j], a1, &wb[j * 2]);
        }
    }
}
__device__ __forceinline__ void mma_group2(uint32_t sb, uint32_t a_base,
                                           uint32_t wh_base, uint32_t wl_base,
                                           float acc[2][4][4],
                                           uint32_t a_row, uint32_t b_row,
                                           uint32_t ahalf, uint32_t bhalf, uint32_t xr) {
#pragma unroll
    for (uint32_t kc = 0; kc < 8; kc++) {
        const uint32_t ach = ((2 * kc + ahalf) ^ xr) << 4;
        const uint32_t bch = ((2 * kc + bhalf) ^ xr) << 4;
        uint32_t a0[4], a1[4], wb[8];
        ldsm4(a0, sb + a_base + a_row + ach);
        ldsm4(a1, sb + a_base + a_row + 4096 + ach);
        ldsm4(&wb[0], sb + wh_base + b_row + bch);
        ldsm4(&wb[4], sb + wh_base + b_row + 4096 + bch);
#pragma unroll
        for (int j = 0; j < 4; j++) {
            mma_bf16(acc[0][j], a0, &wb[j * 2]);
            mma_bf16(acc[1][j], a1, &wb[j * 2]);
        }
        ldsm4(&wb[0], sb + wl_base + b_row + bch);
        ldsm4(&wb[4], sb + wl_base + b_row + 4096 + bch);
#pragma unroll
        for (int j = 0; j < 4; j++) {
            mma_bf16(acc[0][j], a0, &wb[j * 2]);
            mma_bf16(acc[1][j], a1, &wb[j * 2]);
        }
    }
}

// ---------------- conv kernel: fused-AB + C, Ahi double-buffered ----------------
__global__ void __launch_bounds__(CTHR, 1)
conv_mma_kernel(const int* __restrict__ nidx, const int* __restrict__ nmask,
                const float* __restrict__ b1, const float* __restrict__ b2) {
    extern __shared__ char smem[];
    const uint32_t sb = smem_u32(smem);
    const int t = threadIdx.x;
    const int lane = t & 31;
    const int wid = t >> 5;
    const int wm = wid >> 2;        // 0..3 : 32-row band
    const int wn = wid & 3;         // 0..3 : 32-col band
    const int nbase = blockIdx.x * MTILE;
    const size_t ebase = (size_t)nbase * KNB;

    const char* wimg = reinterpret_cast<const char*>(g_Wimg);
    if (t == 0) {
        MBAR_INIT(sb + SM_MB, 1);       // WH (W1h+W2h)
        MBAR_INIT(sb + SM_MB + 8, 1);   // WL (W1l+W2l)
        MBAR_EXPECT_TX(sb + SM_MB, 65536);
        bulk_g2s(sb + SM_WH, wimg + 0, 65536, sb + SM_MB);
        MBAR_EXPECT_TX(sb + SM_MB + 8, 65536);
        bulk_g2s(sb + SM_WL, wimg + 65536, 65536, sb + SM_MB + 8);
    }
    __syncthreads();   // mbar init visible
    stage_A_cp(sb, SM_ALO, g_flo, nidx, nmask, ebase, 0);
    CP_COMMIT();
    stage_A_cp(sb, SM_AHI0, g_fhi, nidx, nmask, ebase, 0);
    CP_COMMIT();

    // per-thread ldmatrix address components
    const uint32_t a_row = (uint32_t)(wm * 32 + (lane & 15)) * 256;
    const uint32_t b_row = (uint32_t)(wn * 32 + ((lane >> 4) << 3) + (lane & 7)) * 256;
    const uint32_t xr = (uint32_t)(lane & 7);
    const uint32_t ahalf = (uint32_t)(lane >> 4);
    const uint32_t bhalf = (uint32_t)((lane >> 3) & 1);

    float acc[2][2][4][4];
#pragma unroll
    for (int c = 0; c < 2; c++)
#pragma unroll
        for (int i = 0; i < 2; i++)
#pragma unroll
            for (int j = 0; j < 4; j++)
#pragma unroll
                for (int q = 0; q < 4; q++) acc[c][i][j][q] = 0.f;

#pragma unroll 1
    for (int k = 0; k < KNB; k++) {
        const uint32_t ph = (uint32_t)(k & 1);
        const bool nxt = (k < KNB - 1);
        const uint32_t ahi_cur = (k & 1) ? SM_AHI1 : SM_AHI0;
        const uint32_t ahi_nxt = (k & 1) ? SM_AHI0 : SM_AHI1;

        // ---- top: Alo[k] + Ahi[k] complete; restage Ahi[k+1] into other buffer ----
        CP_WAIT(0);
        __syncthreads();           // A buffers visible; Ahi[nxt] (k-1's) reads done
        if (nxt) stage_A_cp(sb, ahi_nxt, g_fhi, nidx, nmask, ebase, k + 1);
        CP_COMMIT();

        // ---- fused AB: (Alo + Ahi) x (W1h, W2h) ----
        MBAR_WAIT(sb + SM_MB, ph); // WH[k]
        mma_ab(sb, ahi_cur, acc, a_row, b_row, ahalf, bhalf, xr);

        __syncthreads();           // Alo + WH dead
        if (nxt) stage_A_cp(sb, SM_ALO, g_flo, nidx, nmask, ebase, k + 1);
        CP_COMMIT();
        if (nxt && t == 0) {
            const size_t tb = (size_t)(k + 1) * 131072;
            MBAR_EXPECT_TX(sb + SM_MB, 65536);
            bulk_g2s(sb + SM_WH, wimg + tb, 65536, sb + SM_MB);
        }

        // ---- phase C: Ahi x (W1l, W2l) ----
        MBAR_WAIT(sb + SM_MB + 8, ph); // WL[k]
        mma_c(sb, ahi_cur, acc, a_row, b_row, ahalf, bhalf, xr);

        __syncthreads();           // WL dead
        if (nxt && t == 0) {
            const size_t tb = (size_t)(k + 1) * 131072;
            MBAR_EXPECT_TX(sb + SM_MB + 8, 65536);
            bulk_g2s(sb + SM_WL, wimg + tb + 65536, 65536, sb + SM_MB + 8);
        }
    }

    // epilogue: +bias, relu, store fp32
    const int g = lane >> 2, tig = lane & 3;
#pragma unroll
    for (int c = 0; c < 2; c++) {
        float* outp = c ? g_out2 : g_out1;
        const float* bias = c ? b2 : b1;
#pragma unroll
        for (int j = 0; j < 4; j++) {
            const int col = wn * 32 + j * 8 + tig * 2;
            const float2 bv = *reinterpret_cast<const float2*>(bias + col);
#pragma unroll
            for (int i = 0; i < 2; i++) {
                const int row0 = nbase + wm * 32 + i * 16 + g;
                float2 v0, v1;
                v0.x = fmaxf(acc[c][i][j][0] + bv.x, 0.f);
                v0.y = fmaxf(acc[c][i][j][1] + bv.y, 0.f);
                v1.x = fmaxf(acc[c][i][j][2] + bv.x, 0.f);
                v1.y = fmaxf(acc[c][i][j][3] + bv.y, 0.f);
                *reinterpret_cast<float2*>(outp + (size_t)row0 * DIM + col) = v0;
                *reinterpret_cast<float2*>(outp + (size_t)(row0 + 8) * DIM + col) = v1;
            }
        }
    }
}

// ---------------- segment sums of out2 (+counts); float2 columns ----------
__global__ void segreduce_kernel(const int* __restrict__ segid) {
    const int RPB = 512, QTR = 128;
    const int c2 = threadIdx.x & 63;       // column pair: cols [2*c2, 2*c2+1]
    const int h = threadIdx.x >> 6;        // quarter 0..3
    const int r0 = blockIdx.x * RPB + h * QTR;
    if (r0 >= N_PTS) return;
    const int r1 = min(r0 + QTR, N_PTS);

    float2 sum = make_float2(0.f, 0.f);
    int cur = -1;
    for (int r = r0; r < r1; r++) {
        const int s = segid[r];
        if (s != cur) {
            if (cur >= 0) {
                atomicAdd(&g_segsum[cur * DIM + 2 * c2], sum.x);
                atomicAdd(&g_segsum[cur * DIM + 2 * c2 + 1], sum.y);
            }
            cur = s; sum.x = 0.f; sum.y = 0.f;
        }
        const float2 v = *reinterpret_cast<const float2*>(
            g_out2 + (size_t)r * DIM + 2 * c2);
        sum.x += v.x; sum.y += v.y;
    }
    if (cur >= 0) {
        atomicAdd(&g_segsum[cur * DIM + 2 * c2], sum.x);
        atomicAdd(&g_segsum[cur * DIM + 2 * c2 + 1], sum.y);
    }

    if (c2 == 0) {
        int cnt = 0; cur = -1;
        for (int r = r0; r < r1; r++) {
            const int s = segid[r];
            if (s != cur) {
                if (cur >= 0) atomicAdd(&g_segcnt[cur], cnt);
                cur = s; cnt = 0;
            }
            cnt++;
        }
        if (cur >= 0) atomicAdd(&g_segcnt[cur], cnt);
    }
}

__global__ void segmean_kernel() {
    const int t = threadIdx.x;  // 1024 threads
    const int s = t >> 7;
    const float cnt = fmaxf((float)g_segcnt[s], 1.0f);
    g_segmean[t] = g_segsum[t] / cnt;
}

// ---------------- finalize (tensorized): enc, mid, mid@W3, relu(feats - relu(.)) --
__global__ void __launch_bounds__(NTHR, 2)
finalize_mma_kernel(const float* __restrict__ feats, const int* __restrict__ segid,
                    const float* __restrict__ b3, float* __restrict__ out) {
    extern __shared__ char smem[];
    const uint32_t sb = smem_u32(smem);
    const int t = threadIdx.x;
    const int lane = t & 31;
    const int wid = t >> 5;
    const int nbase = blockIdx.x * FTILE;

    // stage W3 hi/lo images (64KB, linear copy)
    {
        const uint4* src = reinterpret_cast<const uint4*>(g_W3img);
        uint4* dst = reinterpret_cast<uint4*>(smem + FM_W3H);
#pragma unroll
        for (int i = 0; i < 16; i++) dst[t + i * NTHR] = src[t + i * NTHR];
    }

    float* red  = reinterpret_cast<float*>(smem + FM_RED);
    float* rm1s = reinterpret_cast<float*>(smem + FM_RM);

    const int gpt = t & 63, gseg = t >> 6;
    const int n = nbase + gpt;

    const float4* o1p = reinterpret_cast<const float4*>(g_out1 + (size_t)n * DIM) + gseg * 8;
    const float4* o2p = reinterpret_cast<const float4*>(g_out2 + (size_t)n * DIM) + gseg * 8;

    float4 v1[8];
    float psum = 0.f;
#pragma unroll
    for (int q = 0; q < 8; q++) {
        v1[q] = o1p[q];
        psum += v1[q].x + v1[q].y + v1[q].z + v1[q].w;
    }
    red[t] = psum;
    __syncthreads();
    if (t < FTILE)
        rm1s[t] = (red[t] + red[t + 64] + red[t + 128] + red[t + 192]) * (1.0f / 128.0f);
    __syncthreads();

    const float rm = rm1s[gpt];
    const int sg = segid[n];
    const float4* smn = reinterpret_cast<const float4*>(g_segmean + sg * DIM) + gseg * 8;

    // mid = enc + out1 + out2; split to bf16 hi/lo; STS to swizzled A images
    const uint32_t xg = (uint32_t)(gpt & 7);
#pragma unroll
    for (int cc = 0; cc < 4; cc++) {
        float m[8];
#pragma unroll
        for (int h = 0; h < 2; h++) {
            const int q = cc * 2 + h;
            const float4 b = o2p[q];
            const float4 mm = smn[q];
            m[h * 4 + 0] = sqrtf(fmaf(rm, mm.x, 1e-12f)) + v1[q].x + b.x;
            m[h * 4 + 1] = sqrtf(fmaf(rm, mm.y, 1e-12f)) + v1[q].y + b.y;
            m[h * 4 + 2] = sqrtf(fmaf(rm, mm.z, 1e-12f)) + v1[q].z + b.z;
            m[h * 4 + 3] = sqrtf(fmaf(rm, mm.w, 1e-12f)) + v1[q].w + b.w;
        }
        uint4 hi, lo;
        hi.x = packbf2(m[0], m[1]); hi.y = packbf2(m[2], m[3]);
        hi.z = packbf2(m[4], m[5]); hi.w = packbf2(m[6], m[7]);
        float r[8];
#pragma unroll
        for (int e = 0; e < 8; e++)
            r[e] = m[e] - __bfloat162float(__float2bfloat16(m[e]));
        lo.x = packbf2(r[0], r[1]); lo.y = packbf2(r[2], r[3]);
        lo.z = packbf2(r[4], r[5]); lo.w = packbf2(r[6], r[7]);
        const uint32_t c = (uint32_t)(gseg * 4 + cc);
        const uint32_t off = (uint32_t)gpt * 256 + ((c ^ xg) << 4);
        *reinterpret_cast<uint4*>(smem + FM_AH + off) = hi;
        *reinterpret_cast<uint4*>(smem + FM_AL + off) = lo;
    }
    __syncthreads();

    // mma: 8 warps, tile 64(m) x 128(n); warp tile 32x32
    const int wm = wid >> 2;        // 0..1
    const int wn = wid & 3;         // 0..3
    const uint32_t a_row = (uint32_t)(wm * 32 + (lane & 15)) * 256;
    const uint32_t b_row = (uint32_t)(wn * 32 + ((lane >> 4) << 3) + (lane & 7)) * 256;
    const uint32_t xr = (uint32_t)(lane & 7);
    const uint32_t ahalf = (uint32_t)(lane >> 4);
    const uint32_t bhalf = (uint32_t)((lane >> 3) & 1);

    float acc[2][4][4];
#pragma unroll
    for (int i = 0; i < 2; i++)
#pragma unroll
        for (int j = 0; j < 4; j++)
#pragma unroll
            for (int q = 0; q < 4; q++) acc[i][j][q] = 0.f;

    mma_group1(sb, FM_AL, FM_W3H, acc, a_row, b_row, ahalf, bhalf, xr);
    mma_group2(sb, FM_AH, FM_W3H, FM_W3L, acc, a_row, b_row, ahalf, bhalf, xr);

    // epilogue: +b3, relu, feats - , relu, store
    const int g = lane >> 2, tig = lane & 3;
#pragma unroll
    for (int j = 0; j < 4; j++) {
        const int col = wn * 32 + j * 8 + tig * 2;
        const float2 bv = *reinterpret_cast<const float2*>(b3 + col);
#pragma unroll
        for (int i = 0; i < 2; i++) {
            const int row0 = nbase + wm * 32 + i * 16 + g;
            const float2 f0 = *reinterpret_cast<const float2*>(feats + (size_t)row0 * DIM + col);
            const float2 f1 = *reinterpret_cast<const float2*>(feats + (size_t)(row0 + 8) * DIM + col);
            float2 v0, v1r;
            v0.x  = fmaxf(f0.x - fmaxf(acc[i][j][0] + bv.x, 0.f), 0.f);
            v0.y  = fmaxf(f0.y - fmaxf(acc[i][j][1] + bv.y, 0.f), 0.f);
            v1r.x = fmaxf(f1.x - fmaxf(acc[i][j][2] + bv.x, 0.f), 0.f);
            v1r.y = fmaxf(f1.y - fmaxf(acc[i][j][3] + bv.y, 0.f), 0.f);
            *reinterpret_cast<float2*>(out + (size_t)row0 * DIM + col) = v0;
            *reinterpret_cast<float2*>(out + (size_t)(row0 + 8) * DIM + col) = v1r;
        }
    }
}

// ---------------- launch ----------------
extern "C" void kernel_launch(void* const* d_in, const int* in_sizes, int n_in,
                              void* d_out, int out_size) {
    const float* feats = (const float*)d_in[0];
    const int* nidx = (const int*)d_in[1];
    const int* nmask = (const int*)d_in[2];   // bool materialized as int32
    const int* segid = (const int*)d_in[3];
    const int o = (n_in >= 11) ? 1 : 0;
    const float* W1 = (const float*)d_in[4 + o];
    const float* b1 = (const float*)d_in[5 + o];
    const float* W2 = (const float*)d_in[6 + o];
    const float* b2 = (const float*)d_in[7 + o];
    const float* W3 = (const float*)d_in[8 + o];
    const float* b3 = (const float*)d_in[9 + o];
    float* out = (float*)d_out;

    cudaFuncSetAttribute(conv_mma_kernel, cudaFuncAttributeMaxDynamicSharedMemorySize,
                         SM_TOTAL);
    cudaFuncSetAttribute(finalize_mma_kernel, cudaFuncAttributeMaxDynamicSharedMemorySize,
                         FM_TOT);

    pre_pass_kernel<<<PP_TOTAL, NTHR>>>(feats, W1, W2, W3);

    conv_mma_kernel<<<NBLK, CTHR, SM_TOTAL>>>(nidx, nmask, b1, b2);

    segreduce_kernel<<<(N_PTS + 511) / 512, 256>>>(segid);
    segmean_kernel<<<1, 1024>>>();

    finalize_mma_kernel<<<N_PTS / FTILE, NTHR, FM_TOT>>>(feats, segid, b3, out);
}

// round 13
// speedup vs baseline: 1.0314x; 1.0314x over previous
#include <cuda_runtime.h>
#include <cuda_bf16.h>
#include <cstdint>

#define N_PTS 400000
#define DIM   128
#define KNB   27
#define NSEG  8
#define MTILE 128
#define CTHR  512
#define NTHR  256
#define NBLK  (N_PTS / MTILE)
#define FTILE 128
#define FTHR  512

// ---------------- scratch (static device globals: allocation-free) ----------------
__device__ float g_out1[(size_t)N_PTS * DIM];
__device__ float g_out2[(size_t)N_PTS * DIM];
__device__ float g_segsum[NSEG * DIM];
__device__ float g_segmean[NSEG * DIM];
__device__ int   g_segcnt[NSEG];
__device__ __nv_bfloat16 g_fhi[(size_t)N_PTS * DIM];
__device__ __nv_bfloat16 g_flo[(size_t)N_PTS * DIM];
// W images: [k][part(hi/lo)][conv] 32KB tiles -> hi pair contiguous, lo pair contiguous
__device__ __nv_bfloat16 g_Wimg[(size_t)KNB * 2 * 2 * 16384];
// W3 image: [part(hi/lo)] 32KB tiles (128 rows x 256B each)
__device__ __nv_bfloat16 g_W3img[2 * 16384];

// ---------------- smem layout for conv kernel (bytes) ----------------
#define SM_MB   0          // mbars: WH@0 WL@8
#define SM_IDX  64
#define SM_MSK  (SM_IDX + MTILE * KNB * 4)      // 13888
#define SM_AHI  17408
#define SM_ALO  (SM_AHI + 32768)                // 50176
#define SM_WH   (SM_ALO + 32768)                // 82944  (W1h, W2h@+32768)
#define SM_WL   (SM_WH + 65536)                 // 148480 (W1l, W2l@+32768)
#define SM_TOTAL (SM_WL + 65536)                // 214016

// ---------------- smem layout for finalize kernel (bytes) ----------------
#define FM_W3H 0                                // 32KB
#define FM_W3L 32768                            // 32KB
#define FM_AH  65536                            // 32KB (128 rows x 256B)
#define FM_AL  98304                            // 32KB
#define FM_RED 131072                           // 512 floats
#define FM_RM  (FM_RED + FTHR * 4)              // 128 floats
#define FM_TOT (FM_RM + FTILE * 4)              // 133632

// fused pre-pass block ranges
#define PP_ZERO   4
#define PP_SPLIT  ((N_PTS * DIM) / (NTHR * 4))          // 50000
#define PP_W      ((KNB * 2 * DIM * DIM) / NTHR)        // 3456
#define PP_W3     ((DIM * DIM) / NTHR)                  // 64
#define PP_TOTAL  (PP_ZERO + PP_SPLIT + PP_W + PP_W3)   // 53524

__device__ __forceinline__ uint32_t smem_u32(const void* p) {
    return (uint32_t)__cvta_generic_to_shared(p);
}

// ---------------- PTX helpers (baseline sm_80/sm_90 features only) ----------------
#define MBAR_INIT(a, c) \
    asm volatile("mbarrier.init.shared.b64 [%0], %1;" :: "r"(a), "r"(c) : "memory")
#define MBAR_EXPECT_TX(a, b) \
    asm volatile("mbarrier.arrive.expect_tx.shared.b64 _, [%0], %1;" :: "r"(a), "r"(b) : "memory")
#define MBAR_WAIT(a, ph) do {                                                 \
    uint32_t _m = (a), _p = (ph), _d;                                         \
    asm volatile("{\n .reg .pred p;\n"                                        \
        " mbarrier.try_wait.parity.acquire.cta.shared::cta.b64 p, [%1], %2;\n"\
        " selp.b32 %0, 1, 0, p;\n}" : "=r"(_d) : "r"(_m), "r"(_p) : "memory");\
    if (!_d) {                                                                \
        asm volatile("{\n .reg .pred P1;\n"                                   \
        "W%=:\n mbarrier.try_wait.parity.acquire.cta.shared::cta.b64 P1, [%0], %1, 0x989680;\n" \
        " @P1 bra.uni D%=;\n bra.uni W%=;\nD%=:\n}" :: "r"(_m), "r"(_p) : "memory"); \
    } } while (0)

#define CP_COMMIT() asm volatile("cp.async.commit_group;" ::: "memory")
#define CP_WAIT(n)  asm volatile("cp.async.wait_group %0;" :: "n"(n) : "memory")

__device__ __forceinline__ void cp16z(uint32_t dst, const void* src, uint32_t srcsz) {
    asm volatile("cp.async.cg.shared.global [%0], [%1], 16, %2;"
                 :: "r"(dst), "l"(src), "r"(srcsz) : "memory");
}
__device__ __forceinline__ void bulk_g2s(uint32_t dst, const void* src,
                                         uint32_t bytes, uint32_t mbar) {
    asm volatile(
        "cp.async.bulk.shared::cluster.global.mbarrier::complete_tx::bytes "
        "[%0], [%1], %2, [%3];"
        :: "r"(dst), "l"(src), "r"(bytes), "r"(mbar) : "memory");
}
__device__ __forceinline__ void ldsm4(uint32_t* r, uint32_t addr) {
    asm volatile("ldmatrix.sync.aligned.m8n8.x4.shared.b16 {%0,%1,%2,%3}, [%4];"
        : "=r"(r[0]), "=r"(r[1]), "=r"(r[2]), "=r"(r[3]) : "r"(addr));
}
__device__ __forceinline__ void mma_bf16(float* c, const uint32_t* a, const uint32_t* b) {
    asm volatile("mma.sync.aligned.m16n8k16.row.col.f32.bf16.bf16.f32 "
        "{%0,%1,%2,%3}, {%4,%5,%6,%7}, {%8,%9}, {%0,%1,%2,%3};"
        : "+f"(c[0]), "+f"(c[1]), "+f"(c[2]), "+f"(c[3])
        : "r"(a[0]), "r"(a[1]), "r"(a[2]), "r"(a[3]), "r"(b[0]), "r"(b[1]));
}
__device__ __forceinline__ uint32_t packbf2(float lo, float hi) {
    uint32_t r;
    asm("cvt.rn.bf16x2.f32 %0, %1, %2;" : "=r"(r) : "f"(hi), "f"(lo));
    return r;
}

// ---------------- fused pre-pass: zero | split feats | prep W | prep W3 ----------
__global__ void pre_pass_kernel(const float* __restrict__ feats,
                                const float* __restrict__ W1,
                                const float* __restrict__ W2,
                                const float* __restrict__ W3) {
    const uint32_t bid = blockIdx.x;
    const uint32_t tid = threadIdx.x;
    if (bid < PP_ZERO) {
        const uint32_t t = bid * NTHR + tid;   // 0..1023
        if (t < NSEG * DIM) g_segsum[t] = 0.f;
        if (t < NSEG) g_segcnt[t] = 0;
        return;
    }
    if (bid < PP_ZERO + PP_SPLIT) {
        const size_t i = ((size_t)(bid - PP_ZERO) * NTHR + tid) * 4;
        const float4 v = *reinterpret_cast<const float4*>(feats + i);
        const float hx = __bfloat162float(__float2bfloat16(v.x));
        const float hy = __bfloat162float(__float2bfloat16(v.y));
        const float hz = __bfloat162float(__float2bfloat16(v.z));
        const float hw = __bfloat162float(__float2bfloat16(v.w));
        uint2 hi, lo;
        hi.x = packbf2(v.x, v.y);       hi.y = packbf2(v.z, v.w);
        lo.x = packbf2(v.x - hx, v.y - hy);
        lo.y = packbf2(v.z - hz, v.w - hw);
        *reinterpret_cast<uint2*>(g_fhi + i) = hi;
        *reinterpret_cast<uint2*>(g_flo + i) = lo;
        return;
    }
    if (bid < PP_ZERO + PP_SPLIT + PP_W) {
        // W -> transposed, split, SMEM-image; tile index = k*4 + part*2 + conv
        const uint32_t t = (bid - PP_ZERO - PP_SPLIT) * NTHR + tid;
        const uint32_t d = t & 127;
        const uint32_t n = (t >> 7) & 127;
        const uint32_t conv = (t >> 14) & 1;
        const uint32_t k = t >> 15;
        const float w = (conv ? W2 : W1)[((size_t)k * DIM + d) * DIM + n];
        const float hf = __bfloat162float(__float2bfloat16(w));
        const uint32_t off = n * 256 + ((((d >> 3) ^ (n & 7)) << 4)) + (d & 7) * 2;
        const size_t khi = (size_t)(k * 4 + conv);
        const size_t klo = (size_t)(k * 4 + 2 + conv);
        g_Wimg[khi * 16384 + (off >> 1)] = __float2bfloat16(w);
        g_Wimg[klo * 16384 + (off >> 1)] = __float2bfloat16(w - hf);
        return;
    }
    {
        const uint32_t t = (bid - PP_ZERO - PP_SPLIT - PP_W) * NTHR + tid;
        const uint32_t n = t & 127;
        const uint32_t d = t >> 7;
        const float w = W3[(size_t)d * DIM + n];
        const float hf = __bfloat162float(__float2bfloat16(w));
        const uint32_t off = n * 256 + ((((d >> 3) ^ (n & 7)) << 4)) + (d & 7) * 2;
        g_W3img[off >> 1]           = __float2bfloat16(w);
        g_W3img[16384 + (off >> 1)] = __float2bfloat16(w - hf);
    }
}

// ---------------- A staging via cp.async zfill (512 threads, 32KB/part) ----------
__device__ __forceinline__ void stage_A_cp(uint32_t sb, uint32_t a_base,
                                           const __nv_bfloat16* fsrc,
                                           const int* idx_s,
                                           const unsigned char* msk_s, int k) {
    const int t = threadIdx.x;
    const int r = t >> 2;                  // row 0..127
    const int q = t & 3;                   // 4 chunks per thread
    const int id = idx_s[r * KNB + k];
    const uint32_t sz = msk_s[r * KNB + k] ? 16u : 0u;
    const char* src = reinterpret_cast<const char*>(fsrc + (size_t)id * DIM) + q * 64;
    const uint32_t drow = sb + a_base + (uint32_t)r * 256;
    const uint32_t x = (uint32_t)(r & 7);
#pragma unroll
    for (int c2 = 0; c2 < 4; c2++) {
        const uint32_t c = (uint32_t)(q * 4 + c2);
        cp16z(drow + ((c ^ x) << 4), src + c2 * 16, sz);
    }
}

// ---------------- MMA: one A-part x both convs' W tiles (w2 at +32768) ----------
__device__ __forceinline__ void mma_dual(uint32_t sb, uint32_t a_base, uint32_t w_base,
                                         float acc[2][2][4][4],
                                         uint32_t a_row, uint32_t b_row,
                                         uint32_t ahalf, uint32_t bhalf, uint32_t xr) {
#pragma unroll
    for (uint32_t kc = 0; kc < 8; kc++) {
        const uint32_t ach = ((2 * kc + ahalf) ^ xr) << 4;
        const uint32_t bch = ((2 * kc + bhalf) ^ xr) << 4;
        uint32_t a0[4], a1[4], w1[8], w2[8];
        ldsm4(a0, sb + a_base + a_row + ach);
        ldsm4(a1, sb + a_base + a_row + 4096 + ach);
        ldsm4(&w1[0], sb + w_base + b_row + bch);
        ldsm4(&w1[4], sb + w_base + b_row + 4096 + bch);
        ldsm4(&w2[0], sb + w_base + 32768 + b_row + bch);
        ldsm4(&w2[4], sb + w_base + 32768 + b_row + 4096 + bch);
#pragma unroll
        for (int j = 0; j < 4; j++) {
            mma_bf16(acc[0][0][j], a0, &w1[j * 2]);
            mma_bf16(acc[0][1][j], a1, &w1[j * 2]);
            mma_bf16(acc[1][0][j], a0, &w2[j * 2]);
            mma_bf16(acc[1][1][j], a1, &w2[j * 2]);
        }
    }
}

// ---------------- MMA product groups (used by finalize) ----------------
__device__ __forceinline__ void mma_group1(uint32_t sb, uint32_t a_base, uint32_t w_base,
                                           float acc[2][4][4],
                                           uint32_t a_row, uint32_t b_row,
                                           uint32_t ahalf, uint32_t bhalf, uint32_t xr) {
#pragma unroll
    for (uint32_t kc = 0; kc < 8; kc++) {
        const uint32_t ach = ((2 * kc + ahalf) ^ xr) << 4;
        const uint32_t bch = ((2 * kc + bhalf) ^ xr) << 4;
        uint32_t a0[4], a1[4], wb[8];
        ldsm4(a0, sb + a_base + a_row + ach);
        ldsm4(a1, sb + a_base + a_row + 4096 + ach);
        ldsm4(&wb[0], sb + w_base + b_row + bch);
        ldsm4(&wb[4], sb + w_base + b_row + 4096 + bch);
#pragma unroll
        for (int j = 0; j < 4; j++) {
            mma_bf16(acc[0][j], a0, &wb[j * 2]);
            mma_bf16(acc[1][j], a1, &wb[j * 2]);
        }
    }
}
__device__ __forceinline__ void mma_group2(uint32_t sb, uint32_t a_base,
                                           uint32_t wh_base, uint32_t wl_base,
                                           float acc[2][4][4],
                                           uint32_t a_row, uint32_t b_row,
                                           uint32_t ahalf, uint32_t bhalf, uint32_t xr) {
#pragma unroll
    for (uint32_t kc = 0; kc < 8; kc++) {
        const uint32_t ach = ((2 * kc + ahalf) ^ xr) << 4;
        const uint32_t bch = ((2 * kc + bhalf) ^ xr) << 4;
        uint32_t a0[4], a1[4], wb[8];
        ldsm4(a0, sb + a_base + a_row + ach);
        ldsm4(a1, sb + a_base + a_row + 4096 + ach);
        ldsm4(&wb[0], sb + wh_base + b_row + bch);
        ldsm4(&wb[4], sb + wh_base + b_row + 4096 + bch);
#pragma unroll
        for (int j = 0; j < 4; j++) {
            mma_bf16(acc[0][j], a0, &wb[j * 2]);
            mma_bf16(acc[1][j], a1, &wb[j * 2]);
        }
        ldsm4(&wb[0], sb + wl_base + b_row + bch);
        ldsm4(&wb[4], sb + wl_base + b_row + 4096 + bch);
#pragma unroll
        for (int j = 0; j < 4; j++) {
            mma_bf16(acc[0][j], a0, &wb[j * 2]);
            mma_bf16(acc[1][j], a1, &wb[j * 2]);
        }
    }
}

// ---------------- conv kernel: 3-phase dual-conv pipeline (R9/R11, proven) -------
__global__ void __launch_bounds__(CTHR, 1)
conv_mma_kernel(const int* __restrict__ nidx, const int* __restrict__ nmask,
                const float* __restrict__ b1, const float* __restrict__ b2) {
    extern __shared__ char smem[];
    const uint32_t sb = smem_u32(smem);
    const int t = threadIdx.x;
    const int lane = t & 31;
    const int wid = t >> 5;
    const int wm = wid >> 2;        // 0..3 : 32-row band
    const int wn = wid & 3;         // 0..3 : 32-col band
    const int nbase = blockIdx.x * MTILE;

    int* idx_s = reinterpret_cast<int*>(smem + SM_IDX);
    unsigned char* msk_s = reinterpret_cast<unsigned char*>(smem + SM_MSK);

    for (int i = t; i < MTILE * KNB; i += CTHR) {
        idx_s[i] = nidx[(size_t)nbase * KNB + i];
        msk_s[i] = (unsigned char)(nmask[(size_t)nbase * KNB + i] != 0);
    }

    const char* wimg = reinterpret_cast<const char*>(g_Wimg);
    if (t == 0) {
        MBAR_INIT(sb + SM_MB, 1);       // WH (W1h+W2h)
        MBAR_INIT(sb + SM_MB + 8, 1);   // WL (W1l+W2l)
        MBAR_EXPECT_TX(sb + SM_MB, 65536);
        bulk_g2s(sb + SM_WH, wimg + 0, 65536, sb + SM_MB);
        MBAR_EXPECT_TX(sb + SM_MB + 8, 65536);
        bulk_g2s(sb + SM_WL, wimg + 65536, 65536, sb + SM_MB + 8);
    }
    __syncthreads();   // idx_s/msk_s + mbar init visible
    stage_A_cp(sb, SM_ALO, g_flo, idx_s, msk_s, 0);
    CP_COMMIT();
    stage_A_cp(sb, SM_AHI, g_fhi, idx_s, msk_s, 0);
    CP_COMMIT();

    // per-thread ldmatrix address components
    const uint32_t a_row = (uint32_t)(wm * 32 + (lane & 15)) * 256;
    const uint32_t b_row = (uint32_t)(wn * 32 + ((lane >> 4) << 3) + (lane & 7)) * 256;
    const uint32_t xr = (uint32_t)(lane & 7);
    const uint32_t ahalf = (uint32_t)(lane >> 4);
    const uint32_t bhalf = (uint32_t)((lane >> 3) & 1);

    float acc[2][2][4][4];
#pragma unroll
    for (int c = 0; c < 2; c++)
#pragma unroll
        for (int i = 0; i < 2; i++)
#pragma unroll
            for (int j = 0; j < 4; j++)
#pragma unroll
                for (int q = 0; q < 4; q++) acc[c][i][j][q] = 0.f;

#pragma unroll 1
    for (int k = 0; k < KNB; k++) {
        const uint32_t ph = (uint32_t)(k & 1);
        const bool nxt = (k < KNB - 1);

        // ---- phase A: Alo x (W1h, W2h) ----
        CP_WAIT(1);                // Alo[k] done (own); Ahi[k] may fly
        __syncthreads();           // Alo visible to all
        MBAR_WAIT(sb + SM_MB, ph); // WH[k]
        mma_dual(sb, SM_ALO, SM_WH, acc, a_row, b_row, ahalf, bhalf, xr);

        // ---- phase B: Ahi x (W1h, W2h) ----
        CP_WAIT(0);                // Ahi[k] done (own)
        __syncthreads();           // Alo dead CTA-wide + Ahi visible
        if (nxt) stage_A_cp(sb, SM_ALO, g_flo, idx_s, msk_s, k + 1);
        CP_COMMIT();
        mma_dual(sb, SM_AHI, SM_WH, acc, a_row, b_row, ahalf, bhalf, xr);

        // ---- phase C: Ahi x (W1l, W2l) ----
        __syncthreads();           // WH dead
        if (nxt && t == 0) {
            const size_t tb = (size_t)(k + 1) * 131072;
            MBAR_EXPECT_TX(sb + SM_MB, 65536);
            bulk_g2s(sb + SM_WH, wimg + tb, 65536, sb + SM_MB);
        }
        MBAR_WAIT(sb + SM_MB + 8, ph); // WL[k]
        mma_dual(sb, SM_AHI, SM_WL, acc, a_row, b_row, ahalf, bhalf, xr);

        __syncthreads();           // WL + Ahi dead
        if (nxt && t == 0) {
            const size_t tb = (size_t)(k + 1) * 131072;
            MBAR_EXPECT_TX(sb + SM_MB + 8, 65536);
            bulk_g2s(sb + SM_WL, wimg + tb + 65536, 65536, sb + SM_MB + 8);
        }
        if (nxt) stage_A_cp(sb, SM_AHI, g_fhi, idx_s, msk_s, k + 1);
        CP_COMMIT();
    }

    // epilogue: +bias, relu, store fp32
    const int g = lane >> 2, tig = lane & 3;
#pragma unroll
    for (int c = 0; c < 2; c++) {
        float* outp = c ? g_out2 : g_out1;
        const float* bias = c ? b2 : b1;
#pragma unroll
        for (int j = 0; j < 4; j++) {
            const int col = wn * 32 + j * 8 + tig * 2;
            const float2 bv = *reinterpret_cast<const float2*>(bias + col);
#pragma unroll
            for (int i = 0; i < 2; i++) {
                const int row0 = nbase + wm * 32 + i * 16 + g;
                float2 v0, v1;
                v0.x = fmaxf(acc[c][i][j][0] + bv.x, 0.f);
                v0.y = fmaxf(acc[c][i][j][1] + bv.y, 0.f);
                v1.x = fmaxf(acc[c][i][j][2] + bv.x, 0.f);
                v1.y = fmaxf(acc[c][i][j][3] + bv.y, 0.f);
                *reinterpret_cast<float2*>(outp + (size_t)row0 * DIM + col) = v0;
                *reinterpret_cast<float2*>(outp + (size_t)(row0 + 8) * DIM + col) = v1;
            }
        }
    }
}

// ---------------- segment sums of out2 (+counts); float2 columns ----------
__global__ void segreduce_kernel(const int* __restrict__ segid) {
    const int RPB = 512, QTR = 128;
    const int c2 = threadIdx.x & 63;       // column pair: cols [2*c2, 2*c2+1]
    const int h = threadIdx.x >> 6;        // quarter 0..3
    const int r0 = blockIdx.x * RPB + h * QTR;
    if (r0 >= N_PTS) return;
    const int r1 = min(r0 + QTR, N_PTS);

    float2 sum = make_float2(0.f, 0.f);
    int cur = -1;
    for (int r = r0; r < r1; r++) {
        const int s = segid[r];
        if (s != cur) {
            if (cur >= 0) {
                atomicAdd(&g_segsum[cur * DIM + 2 * c2], sum.x);
                atomicAdd(&g_segsum[cur * DIM + 2 * c2 + 1], sum.y);
            }
            cur = s; sum.x = 0.f; sum.y = 0.f;
        }
        const float2 v = *reinterpret_cast<const float2*>(
            g_out2 + (size_t)r * DIM + 2 * c2);
        sum.x += v.x; sum.y += v.y;
    }
    if (cur >= 0) {
        atomicAdd(&g_segsum[cur * DIM + 2 * c2], sum.x);
        atomicAdd(&g_segsum[cur * DIM + 2 * c2 + 1], sum.y);
    }

    if (c2 == 0) {
        int cnt = 0; cur = -1;
        for (int r = r0; r < r1; r++) {
            const int s = segid[r];
            if (s != cur) {
                if (cur >= 0) atomicAdd(&g_segcnt[cur], cnt);
                cur = s; cnt = 0;
            }
            cnt++;
        }
        if (cur >= 0) atomicAdd(&g_segcnt[cur], cnt);
    }
}

__global__ void segmean_kernel() {
    const int t = threadIdx.x;  // 1024 threads
    const int s = t >> 7;
    const float cnt = fmaxf((float)g_segcnt[s], 1.0f);
    g_segmean[t] = g_segsum[t] / cnt;
}

// ---------------- finalize (tensorized, FTILE=128, 512 thr): enc, mid, mid@W3 ----
__global__ void __launch_bounds__(FTHR, 1)
finalize_mma_kernel(const float* __restrict__ feats, const int* __restrict__ segid,
                    const float* __restrict__ b3, float* __restrict__ out) {
    extern __shared__ char smem[];
    const uint32_t sb = smem_u32(smem);
    const int t = threadIdx.x;
    const int lane = t & 31;
    const int wid = t >> 5;
    const int nbase = blockIdx.x * FTILE;

    // stage W3 hi/lo images (64KB, linear copy)
    {
        const uint4* src = reinterpret_cast<const uint4*>(g_W3img);
        uint4* dst = reinterpret_cast<uint4*>(smem + FM_W3H);
#pragma unroll
        for (int i = 0; i < 8; i++) dst[t + i * FTHR] = src[t + i * FTHR];
    }

    float* red  = reinterpret_cast<float*>(smem + FM_RED);
    float* rm1s = reinterpret_cast<float*>(smem + FM_RM);

    const int gpt = t & 127, gseg = t >> 7;   // point in tile, dim quarter
    const int n = nbase + gpt;

    const float4* o1p = reinterpret_cast<const float4*>(g_out1 + (size_t)n * DIM) + gseg * 8;
    const float4* o2p = reinterpret_cast<const float4*>(g_out2 + (size_t)n * DIM) + gseg * 8;

    float4 v1[8];
    float psum = 0.f;
#pragma unroll
    for (int q = 0; q < 8; q++) {
        v1[q] = o1p[q];
        psum += v1[q].x + v1[q].y + v1[q].z + v1[q].w;
    }
    red[t] = psum;
    __syncthreads();
    if (t < FTILE)
        rm1s[t] = (red[t] + red[t + 128] + red[t + 256] + red[t + 384]) * (1.0f / 128.0f);
    __syncthreads();

    const float rm = rm1s[gpt];
    const int sg = segid[n];
    const float4* smn = reinterpret_cast<const float4*>(g_segmean + sg * DIM) + gseg * 8;

    // mid = enc + out1 + out2; split to bf16 hi/lo; STS to swizzled A images
    const uint32_t xg = (uint32_t)(gpt & 7);
#pragma unroll
    for (int cc = 0; cc < 4; cc++) {
        float m[8];
#pragma unroll
        for (int h = 0; h < 2; h++) {
            const int q = cc * 2 + h;
            const float4 b = o2p[q];
            const float4 mm = smn[q];
            m[h * 4 + 0] = sqrtf(fmaf(rm, mm.x, 1e-12f)) + v1[q].x + b.x;
            m[h * 4 + 1] = sqrtf(fmaf(rm, mm.y, 1e-12f)) + v1[q].y + b.y;
            m[h * 4 + 2] = sqrtf(fmaf(rm, mm.z, 1e-12f)) + v1[q].z + b.z;
            m[h * 4 + 3] = sqrtf(fmaf(rm, mm.w, 1e-12f)) + v1[q].w + b.w;
        }
        uint4 hi, lo;
        hi.x = packbf2(m[0], m[1]); hi.y = packbf2(m[2], m[3]);
        hi.z = packbf2(m[4], m[5]); hi.w = packbf2(m[6], m[7]);
        float r[8];
#pragma unroll
        for (int e = 0; e < 8; e++)
            r[e] = m[e] - __bfloat162float(__float2bfloat16(m[e]));
        lo.x = packbf2(r[0], r[1]); lo.y = packbf2(r[2], r[3]);
        lo.z = packbf2(r[4], r[5]); lo.w = packbf2(r[6], r[7]);
        const uint32_t c = (uint32_t)(gseg * 4 + cc);
        const uint32_t off = (uint32_t)gpt * 256 + ((c ^ xg) << 4);
        *reinterpret_cast<uint4*>(smem + FM_AH + off) = hi;
        *reinterpret_cast<uint4*>(smem + FM_AL + off) = lo;
    }
    __syncthreads();

    // mma: 16 warps, tile 128(m) x 128(n); warp tile 32x32 (same map as conv)
    const int wm = wid >> 2;        // 0..3
    const int wn = wid & 3;         // 0..3
    const uint32_t a_row = (uint32_t)(wm * 32 + (lane & 15)) * 256;
    const uint32_t b_row = (uint32_t)(wn * 32 + ((lane >> 4) << 3) + (lane & 7)) * 256;
    const uint32_t xr = (uint32_t)(lane & 7);
    const uint32_t ahalf = (uint32_t)(lane >> 4);
    const uint32_t bhalf = (uint32_t)((lane >> 3) & 1);

    float acc[2][4][4];
#pragma unroll
    for (int i = 0; i < 2; i++)
#pragma unroll
        for (int j = 0; j < 4; j++)
#pragma unroll
            for (int q = 0; q < 4; q++) acc[i][j][q] = 0.f;

    mma_group1(sb, FM_AL, FM_W3H, acc, a_row, b_row, ahalf, bhalf, xr);
    mma_group2(sb, FM_AH, FM_W3H, FM_W3L, acc, a_row, b_row, ahalf, bhalf, xr);

    // epilogue: +b3, relu, feats - , relu, store
    const int g = lane >> 2, tig = lane & 3;
#pragma unroll
    for (int j = 0; j < 4; j++) {
        const int col = wn * 32 + j * 8 + tig * 2;
        const float2 bv = *reinterpret_cast<const float2*>(b3 + col);
#pragma unroll
        for (int i = 0; i < 2; i++) {
            const int row0 = nbase + wm * 32 + i * 16 + g;
            const float2 f0 = *reinterpret_cast<const float2*>(feats + (size_t)row0 * DIM + col);
            const float2 f1 = *reinterpret_cast<const float2*>(feats + (size_t)(row0 + 8) * DIM + col);
            float2 v0, v1r;
            v0.x  = fmaxf(f0.x - fmaxf(acc[i][j][0] + bv.x, 0.f), 0.f);
            v0.y  = fmaxf(f0.y - fmaxf(acc[i][j][1] + bv.y, 0.f), 0.f);
            v1r.x = fmaxf(f1.x - fmaxf(acc[i][j][2] + bv.x, 0.f), 0.f);
            v1r.y = fmaxf(f1.y - fmaxf(acc[i][j][3] + bv.y, 0.f), 0.f);
            *reinterpret_cast<float2*>(out + (size_t)row0 * DIM + col) = v0;
            *reinterpret_cast<float2*>(out + (size_t)(row0 + 8) * DIM + col) = v1r;
        }
    }
}

// ---------------- launch ----------------
extern "C" void kernel_launch(void* const* d_in, const int* in_sizes, int n_in,
                              void* d_out, int out_size) {
    const float* feats = (const float*)d_in[0];
    const int* nidx = (const int*)d_in[1];
    const int* nmask = (const int*)d_in[2];   // bool materialized as int32
    const int* segid = (const int*)d_in[3];
    const int o = (n_in >= 11) ? 1 : 0;
    const float* W1 = (const float*)d_in[4 + o];
    const float* b1 = (const float*)d_in[5 + o];
    const float* W2 = (const float*)d_in[6 + o];
    const float* b2 = (const float*)d_in[7 + o];
    const float* W3 = (const float*)d_in[8 + o];
    const float* b3 = (const float*)d_in[9 + o];
    float* out = (float*)d_out;

    cudaFuncSetAttribute(conv_mma_kernel, cudaFuncAttributeMaxDynamicSharedMemorySize,
                         SM_TOTAL);
    cudaFuncSetAttribute(finalize_mma_kernel, cudaFuncAttributeMaxDynamicSharedMemorySize,
                         FM_TOT);

    pre_pass_kernel<<<PP_TOTAL, NTHR>>>(feats, W1, W2, W3);

    conv_mma_kernel<<<NBLK, CTHR, SM_TOTAL>>>(nidx, nmask, b1, b2);

    segreduce_kernel<<<(N_PTS + 511) / 512, 256>>>(segid);
    segmean_kernel<<<1, 1024>>>();

    finalize_mma_kernel<<<N_PTS / FTILE, FTHR, FM_TOT>>>(feats, segid, b3, out);
}